// round 1
// baseline (speedup 1.0000x reference)
#include <cuda_runtime.h>

// GRU_39170101739852: B=4096, T=512, H=64 GRU + Linear(H->1), fp32.
// Strategy: per-CTA batch tile of 32, sequential over T, per-step 32x192x64
// SIMT GEMM in fp32 using packed fma.rn.f32x2 (Blackwell), weights + h in smem.

#define BB 4096
#define TT 512
#define HH 64
#define GG 192          // 3*H
#define MB 32           // batch rows per CTA
#define NTHREADS 256    // 64 units x 4 batch-tiles
#define NB 8            // batch rows per thread
#define TCHUNK 32       // x staging chunk along T

typedef unsigned long long u64;

__device__ __forceinline__ u64 pack2(float lo, float hi) {
    u64 r; asm("mov.b64 %0, {%1,%2};" : "=l"(r) : "f"(lo), "f"(hi)); return r;
}
__device__ __forceinline__ void unpack2(u64 v, float &lo, float &hi) {
    asm("mov.b64 {%0,%1}, %2;" : "=f"(lo), "=f"(hi) : "l"(v));
}
__device__ __forceinline__ void fma2(u64 &d, u64 a, u64 b) {
    asm("fma.rn.f32x2 %0, %1, %2, %0;" : "+l"(d) : "l"(a), "l"(b));
}
__device__ __forceinline__ float fsig(float v) {
    float e; asm("ex2.approx.f32 %0, %1;" : "=f"(e) : "f"(v * -1.4426950408889634f));
    float r; asm("rcp.approx.f32 %0, %1;" : "=f"(r) : "f"(1.0f + e));
    return r;
}
__device__ __forceinline__ float ftanh(float v) {
    // tanh(v) = 2*sigmoid(2v) - 1
    return fmaf(2.0f, fsig(2.0f * v), -1.0f);
}

// Shared memory layout (floats):
//   wsh : [0, 12288)            W_hh transposed: wsh[k*192 + g]
//   hsh : [12288, 14336)        h state: hsh[b_local*64 + u]
//   xt  : [14336, 15360)        x tile: xt[b_local*32 + (t%32)]
//   red : [15360, 15424)        per-batch partial output sums: red[b_local*2 + half]
#define OFF_W 0
#define OFF_H 12288
#define OFF_X 14336
#define OFF_R 15360
#define SMEM_FLOATS 15424

__global__ void __launch_bounds__(NTHREADS, 1)
gru_kernel(const float* __restrict__ x,
           const float* __restrict__ w_ih,
           const float* __restrict__ w_hh,
           const float* __restrict__ b_ih,
           const float* __restrict__ b_hh,
           const float* __restrict__ w_lin,
           const float* __restrict__ b_lin,
           float* __restrict__ out)
{
    extern __shared__ float smem[];
    float* wsh = smem + OFF_W;
    float* hsh = smem + OFF_H;
    float* xt  = smem + OFF_X;
    float* red = smem + OFF_R;

    const int tid = threadIdx.x;
    const int u   = tid & 63;        // hidden unit
    const int bt  = tid >> 6;        // batch tile 0..3
    const int b0  = bt * NB;         // local batch base
    const int bg  = blockIdx.x * MB; // global batch base

    // Load W_hh transposed into smem: wsh[k*G + g] = w_hh[g*H + k]
    for (int i = tid; i < GG * HH; i += NTHREADS) {
        int g = i >> 6, k = i & 63;
        wsh[k * GG + g] = w_hh[i];
    }
    // Zero h state
    for (int i = tid; i < MB * HH; i += NTHREADS) hsh[i] = 0.0f;

    // Per-thread scalar weights/biases (gates r,z,n of unit u)
    const float wir = w_ih[u], wiz = w_ih[HH + u], win = w_ih[2 * HH + u];
    const float brc = b_ih[u]        + b_hh[u];
    const float bzc = b_ih[HH + u]   + b_hh[HH + u];
    const float bin = b_ih[2 * HH + u];
    const float bhn = b_hh[2 * HH + u];
    const float wlu = w_lin[u];
    const float blv = b_lin[0];

    const u64 br2 = pack2(brc, brc);
    const u64 bz2 = pack2(bzc, bzc);
    const u64 bn2 = pack2(bhn, bhn);

    float hprev[NB];
    #pragma unroll
    for (int j = 0; j < NB; ++j) hprev[j] = 0.0f;

    __syncthreads();

    for (int t = 0; t < TT; ++t) {
        // Stage a 32x32 x-tile every TCHUNK steps (readers gated by sync below)
        if ((t & (TCHUNK - 1)) == 0) {
            int bl = tid >> 3, q = tid & 7;
            float4 v = *reinterpret_cast<const float4*>(&x[(size_t)(bg + bl) * TT + t + q * 4]);
            *reinterpret_cast<float4*>(&xt[bl * TCHUNK + q * 4]) = v;
        }

        // ---- GEMM: acc[g][b] = bias + sum_k W_hh[g][k] * h[b][k] ----
        u64 ar[4], az[4], an[4];   // 4 batch-pairs per gate
        #pragma unroll
        for (int j = 0; j < 4; ++j) { ar[j] = br2; az[j] = bz2; an[j] = bn2; }

        #pragma unroll
        for (int k4 = 0; k4 < HH; k4 += 4) {
            float hvv[NB][4];
            #pragma unroll
            for (int j = 0; j < NB; ++j) {
                float4 hv = *reinterpret_cast<const float4*>(&hsh[(b0 + j) * HH + k4]);
                hvv[j][0] = hv.x; hvv[j][1] = hv.y; hvv[j][2] = hv.z; hvv[j][3] = hv.w;
            }
            #pragma unroll
            for (int kk = 0; kk < 4; ++kk) {
                const int k = k4 + kk;
                const float wr = wsh[k * GG + u];
                const float wz = wsh[k * GG + HH + u];
                const float wn = wsh[k * GG + 2 * HH + u];
                const u64 wr2 = pack2(wr, wr);
                const u64 wz2 = pack2(wz, wz);
                const u64 wn2 = pack2(wn, wn);
                #pragma unroll
                for (int j = 0; j < 4; ++j) {
                    const u64 hp = pack2(hvv[2 * j][kk], hvv[2 * j + 1][kk]);
                    fma2(ar[j], wr2, hp);
                    fma2(az[j], wz2, hp);
                    fma2(an[j], wn2, hp);
                }
            }
        }

        __syncthreads();   // all GEMM reads of hsh done; xt tile visible

        // ---- Epilogue: gates, h update, output partials ----
        float arr[NB], azz[NB], ann[NB];
        #pragma unroll
        for (int j = 0; j < 4; ++j) {
            unpack2(ar[j], arr[2 * j], arr[2 * j + 1]);
            unpack2(az[j], azz[2 * j], azz[2 * j + 1]);
            unpack2(an[j], ann[2 * j], ann[2 * j + 1]);
        }

        const int ttl = t & (TCHUNK - 1);
        float s[NB];
        #pragma unroll
        for (int j = 0; j < NB; ++j) {
            const float xv = xt[(b0 + j) * TCHUNK + ttl];
            const float r  = fsig(fmaf(wir, xv, arr[j]));
            const float z  = fsig(fmaf(wiz, xv, azz[j]));
            const float n  = ftanh(fmaf(r, ann[j], fmaf(win, xv, bin)));
            const float hn = fmaf(z, hprev[j] - n, n);   // (1-z)*n + z*h
            hprev[j] = hn;
            hsh[(b0 + j) * HH + u] = hn;
            s[j] = wlu * hn;
        }

        // Warp-level reduction over 32 units (u spans two warps per batch tile)
        #pragma unroll
        for (int off = 16; off; off >>= 1) {
            #pragma unroll
            for (int j = 0; j < NB; ++j)
                s[j] += __shfl_xor_sync(0xffffffffu, s[j], off);
        }
        if ((tid & 31) == 0) {
            const int half = (tid >> 5) & 1;
            #pragma unroll
            for (int j = 0; j < NB; ++j)
                red[(b0 + j) * 2 + half] = s[j];
        }

        __syncthreads();   // hsh(t) + red visible before next step / finalize

        if (tid < MB) {
            out[(size_t)(bg + tid) * TT + t] = red[tid * 2] + red[tid * 2 + 1] + blv;
        }
    }
}

extern "C" void kernel_launch(void* const* d_in, const int* in_sizes, int n_in,
                              void* d_out, int out_size) {
    const float* x     = (const float*)d_in[0];
    const float* w_ih  = (const float*)d_in[1];
    const float* w_hh  = (const float*)d_in[2];
    const float* b_ih  = (const float*)d_in[3];
    const float* b_hh  = (const float*)d_in[4];
    const float* w_lin = (const float*)d_in[5];
    const float* b_lin = (const float*)d_in[6];
    float* out = (float*)d_out;

    const size_t smem_bytes = SMEM_FLOATS * sizeof(float);
    cudaFuncSetAttribute(gru_kernel, cudaFuncAttributeMaxDynamicSharedMemorySize,
                         (int)smem_bytes);
    gru_kernel<<<BB / MB, NTHREADS, smem_bytes>>>(x, w_ih, w_hh, b_ih, b_hh,
                                                  w_lin, b_lin, out);
}

// round 2
// speedup vs baseline: 1.2098x; 1.2098x over previous
#include <cuda_runtime.h>

// GRU_39170101739852: B=4096, T=512, H=64 GRU + Linear(H->1), fp32.
// R2: k-paired f32x2 accumulation -> zero packing MOVs, LDS.64/128 operands,
// single __syncthreads per timestep via double-buffered h / x / red.

#define BB 4096
#define TT 512
#define HH 64
#define GG 192
#define MB 32           // batch rows per CTA
#define NTHREADS 256    // 64 units x 4 batch-tiles
#define NB 8            // batch rows per thread
#define TCHUNK 32
#define PADW 66         // W row pitch in floats (even -> 8B aligned, 2-way bank conflict)

typedef unsigned long long u64;

__device__ __forceinline__ void fma2(u64 &d, u64 a, u64 b) {
    asm("fma.rn.f32x2 %0, %1, %2, %0;" : "+l"(d) : "l"(a), "l"(b));
}
__device__ __forceinline__ void unpack2(u64 v, float &lo, float &hi) {
    asm("mov.b64 {%0,%1}, %2;" : "=f"(lo), "=f"(hi) : "l"(v));
}
__device__ __forceinline__ float hsum2(u64 v) {
    float lo, hi; unpack2(v, lo, hi); return lo + hi;
}
__device__ __forceinline__ float fsig(float v) {
    float e; asm("ex2.approx.f32 %0, %1;" : "=f"(e) : "f"(v * -1.4426950408889634f));
    float r; asm("rcp.approx.f32 %0, %1;" : "=f"(r) : "f"(1.0f + e));
    return r;
}
__device__ __forceinline__ float ftanh(float v) {
    return fmaf(2.0f, fsig(2.0f * v), -1.0f);
}

// Shared layout (floats):
//   wsh : [0, 12672)   W_hh, row pitch PADW: wsh[g*66 + k]
//   hA  : [12672, +2048)   h state buffer 0: h[b*64 + k]
//   hB  : [14720, +2048)   h state buffer 1
//   xt  : [16768, +2048)   x tiles, double buffered: xt[buf*1024 + b*32 + tt]
//   red : [18816, +128)    output partials, double buffered: red[buf*64 + b*2 + half]
#define OFF_W  0
#define OFF_HA 12672
#define OFF_HB 14720
#define OFF_X  16768
#define OFF_R  18816
#define SMEM_FLOATS 18944

__global__ void __launch_bounds__(NTHREADS, 1)
gru_kernel(const float* __restrict__ x,
           const float* __restrict__ w_ih,
           const float* __restrict__ w_hh,
           const float* __restrict__ b_ih,
           const float* __restrict__ b_hh,
           const float* __restrict__ w_lin,
           const float* __restrict__ b_lin,
           float* __restrict__ out)
{
    extern __shared__ float smem[];
    float* wsh = smem + OFF_W;
    float* hA  = smem + OFF_HA;
    float* hB  = smem + OFF_HB;
    float* xt  = smem + OFF_X;
    float* red = smem + OFF_R;

    const int tid = threadIdx.x;
    const int u   = tid & 63;
    const int bt  = tid >> 6;
    const int b0  = bt * NB;
    const int bg  = blockIdx.x * MB;

    // W_hh into padded smem rows: wsh[g*PADW + k] = w_hh[g*64 + k]
    for (int i = tid; i < GG * HH; i += NTHREADS) {
        int g = i >> 6, k = i & 63;
        wsh[g * PADW + k] = w_hh[i];
    }
    for (int i = tid; i < 2048; i += NTHREADS) { hA[i] = 0.0f; hB[i] = 0.0f; }

    // Stage first x chunk
    {
        int bl = tid >> 3, q = tid & 7;
        float4 v = *reinterpret_cast<const float4*>(&x[(size_t)(bg + bl) * TT + q * 4]);
        *reinterpret_cast<float4*>(&xt[bl * TCHUNK + q * 4]) = v;
    }

    const float wir = w_ih[u], wiz = w_ih[HH + u], win = w_ih[2 * HH + u];
    const float brc = b_ih[u]        + b_hh[u];
    const float bzc = b_ih[HH + u]   + b_hh[HH + u];
    const float bin = b_ih[2 * HH + u];
    const float bhn = b_hh[2 * HH + u];
    const float wlu = w_lin[u];
    const float blv = b_lin[0];

    const float* wr_row = wsh + u * PADW;              // gate r
    const float* wz_row = wsh + (HH + u) * PADW;       // gate z
    const float* wn_row = wsh + (2 * HH + u) * PADW;   // gate n

    float hprev[NB];
    #pragma unroll
    for (int j = 0; j < NB; ++j) hprev[j] = 0.0f;

    __syncthreads();

    int p = 0;
    for (int t = 0; t < TT; ++t) {
        const float* hr = p ? hB : hA;   // read buffer (state at t)
        float*       hw = p ? hA : hB;   // write buffer (state at t+1)
        const float* hrow = hr + b0 * HH;

        // ---- GEMM over k, pairs accumulated in f32x2 halves ----
        u64 ar[NB], az[NB], an[NB];
        #pragma unroll
        for (int j = 0; j < NB; ++j) { ar[j] = 0ull; az[j] = 0ull; an[j] = 0ull; }

        #pragma unroll
        for (int k4 = 0; k4 < HH / 4; ++k4) {
            // h[b][k4*4 .. k4*4+3] as two packed f32x2 per batch
            ulonglong2 hp[NB];
            #pragma unroll
            for (int j = 0; j < NB; ++j)
                hp[j] = *reinterpret_cast<const ulonglong2*>(&hrow[j * HH + k4 * 4]);

            {
                const int k = k4 * 4;
                const u64 wr2 = *reinterpret_cast<const u64*>(&wr_row[k]);
                const u64 wz2 = *reinterpret_cast<const u64*>(&wz_row[k]);
                const u64 wn2 = *reinterpret_cast<const u64*>(&wn_row[k]);
                #pragma unroll
                for (int j = 0; j < NB; ++j) {
                    fma2(ar[j], wr2, hp[j].x);
                    fma2(az[j], wz2, hp[j].x);
                    fma2(an[j], wn2, hp[j].x);
                }
            }
            {
                const int k = k4 * 4 + 2;
                const u64 wr2 = *reinterpret_cast<const u64*>(&wr_row[k]);
                const u64 wz2 = *reinterpret_cast<const u64*>(&wz_row[k]);
                const u64 wn2 = *reinterpret_cast<const u64*>(&wn_row[k]);
                #pragma unroll
                for (int j = 0; j < NB; ++j) {
                    fma2(ar[j], wr2, hp[j].y);
                    fma2(az[j], wz2, hp[j].y);
                    fma2(an[j], wn2, hp[j].y);
                }
            }
        }

        // ---- Epilogue ----
        const int ttl = t & (TCHUNK - 1);
        const float* xcur = xt + ((t >> 5) & 1) * (MB * TCHUNK);
        float s[NB];
        #pragma unroll
        for (int j = 0; j < NB; ++j) {
            const float xv = xcur[(b0 + j) * TCHUNK + ttl];
            const float r  = fsig(fmaf(wir, xv, hsum2(ar[j]) + brc));
            const float z  = fsig(fmaf(wiz, xv, hsum2(az[j]) + bzc));
            const float n  = ftanh(fmaf(r, hsum2(an[j]) + bhn, fmaf(win, xv, bin)));
            const float hn = fmaf(z, hprev[j] - n, n);
            hprev[j] = hn;
            hw[(b0 + j) * HH + u] = hn;
            s[j] = wlu * hn;
        }

        #pragma unroll
        for (int off = 16; off; off >>= 1) {
            #pragma unroll
            for (int j = 0; j < NB; ++j)
                s[j] += __shfl_xor_sync(0xffffffffu, s[j], off);
        }
        float* rcur = red + (t & 1) * 64;
        if ((tid & 31) == 0) {
            const int half = (tid >> 5) & 1;
            #pragma unroll
            for (int j = 0; j < NB; ++j)
                rcur[(b0 + j) * 2 + half] = s[j];
        }

        // Stage next x chunk (into the buffer NOT read until after the sync)
        if (((t + 1) & (TCHUNK - 1)) == 0 && (t + 1) < TT) {
            int bl = tid >> 3, q = tid & 7;
            float4 v = *reinterpret_cast<const float4*>(
                &x[(size_t)(bg + bl) * TT + (t + 1) + q * 4]);
            float* xnext = xt + (((t + 1) >> 5) & 1) * (MB * TCHUNK);
            *reinterpret_cast<float4*>(&xnext[bl * TCHUNK + q * 4]) = v;
        }

        __syncthreads();

        if (tid < MB) {
            out[(size_t)(bg + tid) * TT + t] =
                rcur[tid * 2] + rcur[tid * 2 + 1] + blv;
        }
        p ^= 1;
    }
}

extern "C" void kernel_launch(void* const* d_in, const int* in_sizes, int n_in,
                              void* d_out, int out_size) {
    const float* x     = (const float*)d_in[0];
    const float* w_ih  = (const float*)d_in[1];
    const float* w_hh  = (const float*)d_in[2];
    const float* b_ih  = (const float*)d_in[3];
    const float* b_hh  = (const float*)d_in[4];
    const float* w_lin = (const float*)d_in[5];
    const float* b_lin = (const float*)d_in[6];
    float* out = (float*)d_out;

    const size_t smem_bytes = SMEM_FLOATS * sizeof(float);
    cudaFuncSetAttribute(gru_kernel, cudaFuncAttributeMaxDynamicSharedMemorySize,
                         (int)smem_bytes);
    gru_kernel<<<BB / MB, NTHREADS, smem_bytes>>>(x, w_ih, w_hh, b_ih, b_hh,
                                                  w_lin, b_lin, out);
}

// round 3
// speedup vs baseline: 1.2234x; 1.0112x over previous
#include <cuda_runtime.h>

// GRU_39170101739852: B=4096, T=512, H=64 GRU + Linear(H->1), fp32.
// R3: MB=16 / NB=4 / 2 CTAs per SM (regs<=128) so co-resident CTAs overlap
// each other's epilogue + barrier latency. k-paired f32x2 GEMM as in R2.

#define BB 4096
#define TT 512
#define HH 64
#define GG 192
#define MB 16           // batch rows per CTA
#define NTHREADS 256    // 64 units x 4 batch-tiles
#define NB 4            // batch rows per thread
#define TCHUNK 32
#define PADW 66         // W row pitch (even -> 8B aligned; phase-split on LDS.64)

typedef unsigned long long u64;

__device__ __forceinline__ void fma2(u64 &d, u64 a, u64 b) {
    asm("fma.rn.f32x2 %0, %1, %2, %0;" : "+l"(d) : "l"(a), "l"(b));
}
__device__ __forceinline__ void unpack2(u64 v, float &lo, float &hi) {
    asm("mov.b64 {%0,%1}, %2;" : "=f"(lo), "=f"(hi) : "l"(v));
}
__device__ __forceinline__ float hsum2(u64 v) {
    float lo, hi; unpack2(v, lo, hi); return lo + hi;
}
__device__ __forceinline__ float fsig(float v) {
    float e; asm("ex2.approx.f32 %0, %1;" : "=f"(e) : "f"(v * -1.4426950408889634f));
    float r; asm("rcp.approx.f32 %0, %1;" : "=f"(r) : "f"(1.0f + e));
    return r;
}
__device__ __forceinline__ float ftanh(float v) {
    return fmaf(2.0f, fsig(2.0f * v), -1.0f);
}

// Shared layout (floats):
//   wsh : [0, 12672)       W_hh, pitch PADW: wsh[g*66 + k]
//   hA  : [12672, +1024)   h buffer 0: h[b*64 + k]
//   hB  : [13696, +1024)   h buffer 1
//   xt  : [14720, +1024)   x tiles, double buffered: xt[buf*512 + b*32 + tt]
//   red : [15744, +64)     output partials, double buffered: red[buf*32 + b*2 + half]
#define OFF_W  0
#define OFF_HA 12672
#define OFF_HB 13696
#define OFF_X  14720
#define OFF_R  15744
#define SMEM_FLOATS 15808

__global__ void __launch_bounds__(NTHREADS, 2)
gru_kernel(const float* __restrict__ x,
           const float* __restrict__ w_ih,
           const float* __restrict__ w_hh,
           const float* __restrict__ b_ih,
           const float* __restrict__ b_hh,
           const float* __restrict__ w_lin,
           const float* __restrict__ b_lin,
           float* __restrict__ out)
{
    extern __shared__ float smem[];
    float* wsh = smem + OFF_W;
    float* hA  = smem + OFF_HA;
    float* hB  = smem + OFF_HB;
    float* xt  = smem + OFF_X;
    float* red = smem + OFF_R;

    const int tid = threadIdx.x;
    const int u   = tid & 63;
    const int bt  = tid >> 6;
    const int b0  = bt * NB;
    const int bg  = blockIdx.x * MB;

    // W_hh into padded smem rows
    for (int i = tid; i < GG * HH; i += NTHREADS) {
        int g = i >> 6, k = i & 63;
        wsh[g * PADW + k] = w_hh[i];
    }
    for (int i = tid; i < MB * HH; i += NTHREADS) { hA[i] = 0.0f; hB[i] = 0.0f; }

    // Stage first x chunk: 16 rows x 32 t = 128 float4
    if (tid < 128) {
        int bl = tid >> 3, q = tid & 7;
        float4 v = *reinterpret_cast<const float4*>(&x[(size_t)(bg + bl) * TT + q * 4]);
        *reinterpret_cast<float4*>(&xt[bl * TCHUNK + q * 4]) = v;
    }

    const float wir = w_ih[u], wiz = w_ih[HH + u], win = w_ih[2 * HH + u];
    const float brc = b_ih[u]        + b_hh[u];
    const float bzc = b_ih[HH + u]   + b_hh[HH + u];
    const float bin = b_ih[2 * HH + u];
    const float bhn = b_hh[2 * HH + u];
    const float wlu = w_lin[u];
    const float blv = b_lin[0];

    const float* wr_row = wsh + u * PADW;
    const float* wz_row = wsh + (HH + u) * PADW;
    const float* wn_row = wsh + (2 * HH + u) * PADW;

    float hprev[NB];
    #pragma unroll
    for (int j = 0; j < NB; ++j) hprev[j] = 0.0f;

    __syncthreads();

    int p = 0;
    for (int t = 0; t < TT; ++t) {
        const float* hr = p ? hB : hA;
        float*       hw = p ? hA : hB;
        const float* hrow = hr + b0 * HH;

        // ---- GEMM over k, pairs accumulated in f32x2 halves ----
        u64 ar[NB], az[NB], an[NB];
        #pragma unroll
        for (int j = 0; j < NB; ++j) { ar[j] = 0ull; az[j] = 0ull; an[j] = 0ull; }

        #pragma unroll
        for (int k4 = 0; k4 < HH / 4; ++k4) {
            ulonglong2 hp[NB];
            #pragma unroll
            for (int j = 0; j < NB; ++j)
                hp[j] = *reinterpret_cast<const ulonglong2*>(&hrow[j * HH + k4 * 4]);

            {
                const int k = k4 * 4;
                const u64 wr2 = *reinterpret_cast<const u64*>(&wr_row[k]);
                const u64 wz2 = *reinterpret_cast<const u64*>(&wz_row[k]);
                const u64 wn2 = *reinterpret_cast<const u64*>(&wn_row[k]);
                #pragma unroll
                for (int j = 0; j < NB; ++j) {
                    fma2(ar[j], wr2, hp[j].x);
                    fma2(az[j], wz2, hp[j].x);
                    fma2(an[j], wn2, hp[j].x);
                }
            }
            {
                const int k = k4 * 4 + 2;
                const u64 wr2 = *reinterpret_cast<const u64*>(&wr_row[k]);
                const u64 wz2 = *reinterpret_cast<const u64*>(&wz_row[k]);
                const u64 wn2 = *reinterpret_cast<const u64*>(&wn_row[k]);
                #pragma unroll
                for (int j = 0; j < NB; ++j) {
                    fma2(ar[j], wr2, hp[j].y);
                    fma2(az[j], wz2, hp[j].y);
                    fma2(an[j], wn2, hp[j].y);
                }
            }
        }

        // ---- Epilogue ----
        const int ttl = t & (TCHUNK - 1);
        const float* xcur = xt + ((t >> 5) & 1) * (MB * TCHUNK);
        float s[NB];
        #pragma unroll
        for (int j = 0; j < NB; ++j) {
            const float xv = xcur[(b0 + j) * TCHUNK + ttl];
            const float r  = fsig(fmaf(wir, xv, hsum2(ar[j]) + brc));
            const float z  = fsig(fmaf(wiz, xv, hsum2(az[j]) + bzc));
            const float n  = ftanh(fmaf(r, hsum2(an[j]) + bhn, fmaf(win, xv, bin)));
            const float hn = fmaf(z, hprev[j] - n, n);
            hprev[j] = hn;
            hw[(b0 + j) * HH + u] = hn;
            s[j] = wlu * hn;
        }

        #pragma unroll
        for (int off = 16; off; off >>= 1) {
            #pragma unroll
            for (int j = 0; j < NB; ++j)
                s[j] += __shfl_xor_sync(0xffffffffu, s[j], off);
        }
        float* rcur = red + (t & 1) * (MB * 2);
        if ((tid & 31) == 0) {
            const int half = (tid >> 5) & 1;
            #pragma unroll
            for (int j = 0; j < NB; ++j)
                rcur[(b0 + j) * 2 + half] = s[j];
        }

        // Stage next x chunk
        if (((t + 1) & (TCHUNK - 1)) == 0 && (t + 1) < TT && tid < 128) {
            int bl = tid >> 3, q = tid & 7;
            float4 v = *reinterpret_cast<const float4*>(
                &x[(size_t)(bg + bl) * TT + (t + 1) + q * 4]);
            float* xnext = xt + (((t + 1) >> 5) & 1) * (MB * TCHUNK);
            *reinterpret_cast<float4*>(&xnext[bl * TCHUNK + q * 4]) = v;
        }

        __syncthreads();

        if (tid < MB) {
            out[(size_t)(bg + tid) * TT + t] =
                rcur[tid * 2] + rcur[tid * 2 + 1] + blv;
        }
        p ^= 1;
    }
}

extern "C" void kernel_launch(void* const* d_in, const int* in_sizes, int n_in,
                              void* d_out, int out_size) {
    const float* x     = (const float*)d_in[0];
    const float* w_ih  = (const float*)d_in[1];
    const float* w_hh  = (const float*)d_in[2];
    const float* b_ih  = (const float*)d_in[3];
    const float* b_hh  = (const float*)d_in[4];
    const float* w_lin = (const float*)d_in[5];
    const float* b_lin = (const float*)d_in[6];
    float* out = (float*)d_out;

    const size_t smem_bytes = SMEM_FLOATS * sizeof(float);
    cudaFuncSetAttribute(gru_kernel, cudaFuncAttributeMaxDynamicSharedMemorySize,
                         (int)smem_bytes);
    gru_kernel<<<BB / MB, NTHREADS, smem_bytes>>>(x, w_ih, w_hh, b_ih, b_hh,
                                                  w_lin, b_lin, out);
}